// round 13
// baseline (speedup 1.0000x reference)
#include <cuda_runtime.h>
#include <cstdint>

#define HID 2048
#define SEQ 2048
#define BATCH 2
#define NH 16
#define HD 128
#define MTOT (BATCH*SEQ)   /* 4096 */
#define HID2 (HID/2)

// ---------------- scratch (no allocations allowed) ----------------
__device__ uint32_t g_Hh[MTOT*HID2],  g_Hl[MTOT*HID2];    // hidden, bf16x2 packed along K
__device__ uint32_t g_Wqh[HID2*HID],  g_Wql[HID2*HID];    // weights, packed along K
__device__ uint32_t g_Woh[HID2*HID],  g_Wol[HID2*HID];
__device__ uint32_t g_Wkh[HID2*HD],   g_Wkl[HID2*HD];
__device__ uint32_t g_Wvh[HID2*HD],   g_Wvl[HID2*HD];
__device__ uint32_t g_Qt[MTOT*HID];                       // Q tf32, scale folded
__device__ uint32_t g_Kt[MTOT*HD],    g_Vt[MTOT*HD];      // K,V tf32
__device__ uint32_t g_Ah[MTOT*HID2],  g_Al[MTOT*HID2];    // attn out, bf16x2 packed

// ---------------- numeric helpers ----------------
__device__ __forceinline__ uint32_t f2tf(float x) {
    uint32_t r; asm("cvt.rna.tf32.f32 %0, %1;" : "=r"(r) : "f"(x)); return r;
}
__device__ __forceinline__ uint16_t f2bf(float x) {
    uint16_t r; asm("cvt.rn.bf16.f32 %0, %1;" : "=h"(r) : "f"(x)); return r;
}
__device__ __forceinline__ float bf2f(uint16_t b) {
    return __uint_as_float(((uint32_t)b) << 16);
}
__device__ __forceinline__ void packsplit_bf(float x0, float x1, uint32_t &hi, uint32_t &lo) {
    uint16_t h0 = f2bf(x0), h1 = f2bf(x1);
    hi = (uint32_t)h0 | ((uint32_t)h1 << 16);
    uint16_t l0 = f2bf(x0 - bf2f(h0)), l1 = f2bf(x1 - bf2f(h1));
    lo = (uint32_t)l0 | ((uint32_t)l1 << 16);
}
__device__ __forceinline__ void mma8(float* d, const uint32_t* a, uint32_t b0, uint32_t b1) {
    asm volatile(
        "mma.sync.aligned.m16n8k8.row.col.f32.tf32.tf32.f32 "
        "{%0,%1,%2,%3}, {%4,%5,%6,%7}, {%8,%9}, {%0,%1,%2,%3};"
        : "+f"(d[0]), "+f"(d[1]), "+f"(d[2]), "+f"(d[3])
        : "r"(a[0]), "r"(a[1]), "r"(a[2]), "r"(a[3]), "r"(b0), "r"(b1));
}
__device__ __forceinline__ void mma16(float* d, const uint32_t* a, uint32_t b0, uint32_t b1) {
    asm volatile(
        "mma.sync.aligned.m16n8k16.row.col.f32.bf16.bf16.f32 "
        "{%0,%1,%2,%3}, {%4,%5,%6,%7}, {%8,%9}, {%0,%1,%2,%3};"
        : "+f"(d[0]), "+f"(d[1]), "+f"(d[2]), "+f"(d[3])
        : "r"(a[0]), "r"(a[1]), "r"(a[2]), "r"(a[3]), "r"(b0), "r"(b1));
}
__device__ __forceinline__ uint32_t s2u(const void* p) {
    return (uint32_t)__cvta_generic_to_shared(p);
}
__device__ __forceinline__ void cp16(uint32_t dst, const void* src) {
    asm volatile("cp.async.cg.shared.global [%0], [%1], 16;" :: "r"(dst), "l"(src));
}
#define CP_COMMIT  asm volatile("cp.async.commit_group;" ::: "memory")
#define CP_WAIT(n) asm volatile("cp.async.wait_group %0;" :: "n"(n) : "memory")

// ---------------- one-time pack (ALL arrays, single launch) ----------------
__global__ void pack_all(
    const float* __restrict__ H,  const float* __restrict__ Wq,
    const float* __restrict__ Wk, const float* __restrict__ Wv,
    const float* __restrict__ Wo,
    uint32_t* __restrict__ Hh,  uint32_t* __restrict__ Hl,
    uint32_t* __restrict__ Wqh, uint32_t* __restrict__ Wql,
    uint32_t* __restrict__ Wkh, uint32_t* __restrict__ Wkl,
    uint32_t* __restrict__ Wvh, uint32_t* __restrict__ Wvl,
    uint32_t* __restrict__ Woh, uint32_t* __restrict__ Wol)
{
    int i = blockIdx.x * 256 + threadIdx.x;
    const int nH = MTOT * HID2, nQ = HID2 * HID, nK = HID2 * HD;
    if (i < nH) {
        float2 v = ((const float2*)H)[i];
        packsplit_bf(v.x, v.y, Hh[i], Hl[i]);
    } else if ((i -= nH) < nQ) {
        int kp = i / HID, n = i - kp * HID;
        packsplit_bf(Wq[(size_t)(2 * kp) * HID + n], Wq[(size_t)(2 * kp + 1) * HID + n],
                     Wqh[i], Wql[i]);
    } else if ((i -= nQ) < nK) {
        int kp = i / HD, n = i - kp * HD;
        packsplit_bf(Wk[(size_t)(2 * kp) * HD + n], Wk[(size_t)(2 * kp + 1) * HD + n],
                     Wkh[i], Wkl[i]);
    } else if ((i -= nK) < nK) {
        int kp = i / HD, n = i - kp * HD;
        packsplit_bf(Wv[(size_t)(2 * kp) * HD + n], Wv[(size_t)(2 * kp + 1) * HD + n],
                     Wvh[i], Wvl[i]);
    } else if ((i -= nK) < nQ) {
        int kp = i / HID, n = i - kp * HID;
        packsplit_bf(Wo[(size_t)(2 * kp) * HID + n], Wo[(size_t)(2 * kp + 1) * HID + n],
                     Woh[i], Wol[i]);
    }
}

// ======================================================================
// bf16x3 GEMM, 512 threads / 16 warps (unchanged from R12 — proven).
// ======================================================================
#define SA 20
#define SB 136
#define GEMM_SMEM(MT) ((4*(128*(MT))*SA + 4*16*SB) * 4)

template<int MT, int TFOUT>
__global__ __launch_bounds__(512) void gemm_bf3(
    const uint32_t* __restrict__ Ahp, const uint32_t* __restrict__ Alp,
    const uint32_t* __restrict__ Bh0, const uint32_t* __restrict__ Bl0,
    const float* __restrict__ bias0, void* __restrict__ C0,
    const uint32_t* __restrict__ Bh1, const uint32_t* __restrict__ Bl1,
    const float* __restrict__ bias1, void* __restrict__ C1,
    int N, int K, float prescale)
{
    constexpr int BM   = 128 * MT;
    constexpr int ASTG = BM * SA;
    constexpr int BSTG = 16 * SB;

    extern __shared__ uint32_t smg[];
    uint32_t* sAh = smg;
    uint32_t* sAl = sAh + 2*ASTG;
    uint32_t* sBh = sAl + 2*ASTG;
    uint32_t* sBl = sBh + 2*BSTG;
    const uint32_t aAh = s2u(sAh), aAl = s2u(sAl);
    const uint32_t aBh = s2u(sBh), aBl = s2u(sBl);

    const uint32_t* Bh   = blockIdx.z ? Bh1   : Bh0;
    const uint32_t* Bl   = blockIdx.z ? Bl1   : Bl0;
    const float*    bias = blockIdx.z ? bias1 : bias0;
    void*           C    = blockIdx.z ? C1    : C0;

    const int tid  = threadIdx.x;
    const int lane = tid & 31, wid = tid >> 5;
    const int g = lane >> 2, t = lane & 3;
    const int wm = (wid >> 1) * (16 * MT);
    const int wn = (wid & 1) * 64;
    const int row0 = blockIdx.y * BM;
    const int col0 = blockIdx.x * 128;
    const int K2 = K >> 1;

    float acc[MT][8][4];
    #pragma unroll
    for (int i = 0; i < MT; i++)
        #pragma unroll
        for (int j = 0; j < 8; j++)
            #pragma unroll
            for (int c = 0; c < 4; c++) acc[i][j][c] = 0.f;

    auto load_stage = [&](int kp0, int st) {
        #pragma unroll
        for (int j = 0; j < MT; j++) {
            int idx = tid + j * 512;
            int r = idx >> 2, c = (idx & 3) * 4;
            size_t go = (size_t)(row0 + r) * K2 + kp0 + c;
            uint32_t so = (uint32_t)(st * ASTG + r * SA + c) * 4;
            cp16(aAh + so, Ahp + go);
            cp16(aAl + so, Alp + go);
        }
        {
            int r = tid >> 5, c = (tid & 31) * 4;
            size_t go = (size_t)(kp0 + r) * N + col0 + c;
            uint32_t so = (uint32_t)(st * BSTG + r * SB + c) * 4;
            cp16(aBh + so, Bh + go);
            cp16(aBl + so, Bl + go);
        }
    };

    const int NIT = K / 32;
    load_stage(0, 0); CP_COMMIT;

    for (int it = 0; it < NIT; ++it) {
        const int st = it & 1;
        if (it + 1 < NIT) { load_stage((it + 1) * 16, st ^ 1); CP_COMMIT; CP_WAIT(1); }
        else              { CP_WAIT(0); }
        __syncthreads();

        const uint32_t* Ah_s = sAh + st * ASTG;
        const uint32_t* Al_s = sAl + st * ASTG;
        const uint32_t* Bh_s = sBh + st * BSTG;
        const uint32_t* Bl_s = sBl + st * BSTG;

        #pragma unroll
        for (int s = 0; s < 2; s++) {
            const int kb = s * 8;
            uint32_t ah[MT][4], al[MT][4];
            #pragma unroll
            for (int mt = 0; mt < MT; mt++) {
                int rm = wm + mt * 16 + g;
                ah[mt][0] = Ah_s[rm * SA + kb + t];
                ah[mt][1] = Ah_s[(rm + 8) * SA + kb + t];
                ah[mt][2] = Ah_s[rm * SA + kb + t + 4];
                ah[mt][3] = Ah_s[(rm + 8) * SA + kb + t + 4];
                al[mt][0] = Al_s[rm * SA + kb + t];
                al[mt][1] = Al_s[(rm + 8) * SA + kb + t];
                al[mt][2] = Al_s[rm * SA + kb + t + 4];
                al[mt][3] = Al_s[(rm + 8) * SA + kb + t + 4];
            }
            #pragma unroll
            for (int nt = 0; nt < 8; nt++) {
                int cn = wn + nt * 8 + g;
                uint32_t bh0 = Bh_s[(kb + t) * SB + cn];
                uint32_t bh1 = Bh_s[(kb + t + 4) * SB + cn];
                uint32_t bl0 = Bl_s[(kb + t) * SB + cn];
                uint32_t bl1 = Bl_s[(kb + t + 4) * SB + cn];
                #pragma unroll
                for (int mt = 0; mt < MT; mt++) {
                    mma16(acc[mt][nt], ah[mt], bh0, bh1);
                    mma16(acc[mt][nt], al[mt], bh0, bh1);
                    mma16(acc[mt][nt], ah[mt], bl0, bl1);
                }
            }
        }
        __syncthreads();
    }

    #pragma unroll
    for (int mt = 0; mt < MT; mt++) {
        int row = row0 + wm + mt * 16 + g;
        #pragma unroll
        for (int nt = 0; nt < 8; nt++) {
            int col = col0 + wn + nt * 8 + 2 * t;
            float bx = bias[col], by = bias[col + 1];
            float v00 = acc[mt][nt][0] + bx, v01 = acc[mt][nt][1] + by;
            float v10 = acc[mt][nt][2] + bx, v11 = acc[mt][nt][3] + by;
            if (TFOUT) {
                uint32_t* Cu = (uint32_t*)C;
                uint2 a = { f2tf(v00 * prescale), f2tf(v01 * prescale) };
                uint2 b = { f2tf(v10 * prescale), f2tf(v11 * prescale) };
                *(uint2*)(Cu + (size_t)row * N + col)       = a;
                *(uint2*)(Cu + (size_t)(row + 8) * N + col) = b;
            } else {
                float* Cf = (float*)C;
                *(float2*)(Cf + (size_t)row * N + col)       = make_float2(v00, v01);
                *(float2*)(Cf + (size_t)(row + 8) * N + col) = make_float2(v10, v11);
            }
        }
    }
}

// ======================================================================
// Flash attention, tf32 mma, WARP-PAIR SPLIT: 512 thr / 16 warps.
// Warp (pair, half): pair owns q rows [16p,16p+16); QK splits keys
// (half*32..+32), PV splits d (half*64..+64). Stats merged via smem.
// Per-thread state halves (s 16, o 32 regs) -> 4 warps/SMSP.
// ======================================================================
#define SQm 132
#define SKm 132
#define SVm 136
#define SPm 68
#define ATTN_SMEM ((128*SQm + 2*64*SKm + 64*SVm + 128*SPm + 512) * 4)  /* 206848 B */

__global__ __launch_bounds__(512) void attn_tf32(
    const uint32_t* __restrict__ Qt, const uint32_t* __restrict__ Kt,
    const uint32_t* __restrict__ Vt,
    uint32_t* __restrict__ OutH, uint32_t* __restrict__ OutL)
{
    extern __shared__ uint32_t sm[];
    uint32_t* Qs = sm;                    // 128 x SQm
    uint32_t* Ks = Qs + 128 * SQm;        // 2 x 64 x SKm
    uint32_t* Vs = Ks + 2 * 64 * SKm;     // 64 x SVm
    uint32_t* Ps = Vs + 64 * SVm;         // 128 x SPm
    float* st_max = (float*)(Ps + 128 * SPm);   // 128 x 2
    float* st_sum = st_max + 256;               // 128 x 2
    const uint32_t aQ = s2u(Qs), aK = s2u(Ks), aV = s2u(Vs);

    const int tid  = threadIdx.x;
    const int lane = tid & 31, warp = tid >> 5;
    const int g = lane >> 2, t = lane & 3;
    const int pair = warp >> 1, half = warp & 1;
    const int qt = blockIdx.x, h = blockIdx.y, b = blockIdx.z;

    const size_t qbase = ((size_t)(b * SEQ + qt * 128)) * HID + h * HD;
    const size_t kvb   = (size_t)b * SEQ * HD;

    auto load_K = [&](int tile, int st) {
        #pragma unroll
        for (int j = 0; j < 4; j++) {
            int idx = tid + j * 512;
            int r = idx >> 5, c = (idx & 31) * 4;
            cp16(aK + (uint32_t)(st * 64 * SKm + r * SKm + c) * 4,
                 Kt + kvb + (size_t)(tile * 64 + r) * HD + c);
        }
    };
    auto load_V = [&](int tile) {
        #pragma unroll
        for (int j = 0; j < 4; j++) {
            int idx = tid + j * 512;
            int r = idx >> 5, c = (idx & 31) * 4;
            cp16(aV + (uint32_t)(r * SVm + c) * 4,
                 Vt + kvb + (size_t)(tile * 64 + r) * HD + c);
        }
    };

    // prologue: Q + K0 + V0 in one group
    #pragma unroll
    for (int j = 0; j < 8; j++) {
        int idx = tid + j * 512;
        int r = idx >> 5, c = (idx & 31) * 4;
        cp16(aQ + (uint32_t)(r * SQm + c) * 4, Qt + qbase + (size_t)r * HID + c);
    }
    load_K(0, 0);
    load_V(0);
    CP_COMMIT;

    float mrow[2] = { -1e30f, -1e30f };
    float lrow[2] = { 0.f, 0.f };
    float o[8][4];
    #pragma unroll
    for (int nt = 0; nt < 8; nt++)
        #pragma unroll
        for (int c = 0; c < 4; c++) o[nt][c] = 0.f;

    const int r0 = pair * 16 + g, r1 = r0 + 8;
    const int prow0 = r0 * SPm, prow1 = r1 * SPm;
    const int NT = SEQ / 64;

    for (int kt = 0; kt < NT; kt++) {
        if (kt == 0) { CP_WAIT(0); } else { CP_WAIT(1); }   // K(kt) ready
        __syncthreads();

        // ---- S(16 x 32-own-keys) = Q_strip @ K_half^T ----
        const uint32_t* Kst = Ks + (kt & 1) * 64 * SKm;
        float s[4][4];
        #pragma unroll
        for (int nt = 0; nt < 4; nt++)
            #pragma unroll
            for (int c = 0; c < 4; c++) s[nt][c] = 0.f;

        #pragma unroll
        for (int ks = 0; ks < 16; ks++) {
            const int kb = ks * 8;
            uint32_t a[4];
            a[0] = Qs[r0 * SQm + kb + t];
            a[1] = Qs[r1 * SQm + kb + t];
            a[2] = Qs[r0 * SQm + kb + t + 4];
            a[3] = Qs[r1 * SQm + kb + t + 4];
            #pragma unroll
            for (int nt = 0; nt < 4; nt++) {
                int cn = half * 32 + nt * 8 + g;
                uint32_t b0 = Kst[cn * SKm + kb + t];
                uint32_t b1 = Kst[cn * SKm + kb + t + 4];
                mma8(s[nt], a, b0, b1);
            }
        }

        // prefetch K(kt+1) (overlaps softmax + PV)
        if (kt + 1 < NT) { load_K(kt + 1, (kt + 1) & 1); CP_COMMIT; }

        // ---- partial row max (own 32 keys), exchange across pair ----
        float tm0 = -1e30f, tm1 = -1e30f;
        #pragma unroll
        for (int nt = 0; nt < 4; nt++) {
            tm0 = fmaxf(tm0, fmaxf(s[nt][0], s[nt][1]));
            tm1 = fmaxf(tm1, fmaxf(s[nt][2], s[nt][3]));
        }
        tm0 = fmaxf(tm0, __shfl_xor_sync(0xffffffffu, tm0, 1));
        tm0 = fmaxf(tm0, __shfl_xor_sync(0xffffffffu, tm0, 2));
        tm1 = fmaxf(tm1, __shfl_xor_sync(0xffffffffu, tm1, 1));
        tm1 = fmaxf(tm1, __shfl_xor_sync(0xffffffffu, tm1, 2));
        if (t == 0) {
            st_max[r0 * 2 + half] = tm0;
            st_max[r1 * 2 + half] = tm1;
        }
        __syncthreads();
        tm0 = fmaxf(tm0, st_max[r0 * 2 + (half ^ 1)]);
        tm1 = fmaxf(tm1, st_max[r1 * 2 + (half ^ 1)]);

        float mn0 = fmaxf(mrow[0], tm0), mn1 = fmaxf(mrow[1], tm1);
        float f0 = __expf(mrow[0] - mn0), f1 = __expf(mrow[1] - mn1);
        mrow[0] = mn0; mrow[1] = mn1;
        lrow[0] *= f0; lrow[1] *= f1;
        #pragma unroll
        for (int nt = 0; nt < 8; nt++) {
            o[nt][0] *= f0; o[nt][1] *= f0;
            o[nt][2] *= f1; o[nt][3] *= f1;
        }

        // ---- exp own keys, write P half, exchange partial sums ----
        float ps0 = 0.f, ps1 = 0.f;
        #pragma unroll
        for (int nt = 0; nt < 4; nt++) {
            int col = half * 32 + nt * 8 + 2 * t;
            float p0 = __expf(s[nt][0] - mn0); ps0 += p0;
            float p1 = __expf(s[nt][1] - mn0); ps0 += p1;
            float p2 = __expf(s[nt][2] - mn1); ps1 += p2;
            float p3 = __expf(s[nt][3] - mn1); ps1 += p3;
            Ps[prow0 + col]     = f2tf(p0);
            Ps[prow0 + col + 1] = f2tf(p1);
            Ps[prow1 + col]     = f2tf(p2);
            Ps[prow1 + col + 1] = f2tf(p3);
        }
        ps0 += __shfl_xor_sync(0xffffffffu, ps0, 1);
        ps0 += __shfl_xor_sync(0xffffffffu, ps0, 2);
        ps1 += __shfl_xor_sync(0xffffffffu, ps1, 1);
        ps1 += __shfl_xor_sync(0xffffffffu, ps1, 2);
        if (t == 0) {
            st_sum[r0 * 2 + half] = ps0;
            st_sum[r1 * 2 + half] = ps1;
        }

        // V(kt) ready + P/st_sum visibility in one barrier
        if (kt + 1 < NT) { CP_WAIT(1); } else { CP_WAIT(0); }
        __syncthreads();

        ps0 += st_sum[r0 * 2 + (half ^ 1)];
        ps1 += st_sum[r1 * 2 + (half ^ 1)];
        lrow[0] += ps0; lrow[1] += ps1;

        // ---- O(16 x 64-own-d) += P(16x64 full) @ V_half(64x64) ----
        #pragma unroll
        for (int ks = 0; ks < 8; ks++) {
            const int kb = ks * 8;
            uint32_t a[4];
            a[0] = Ps[prow0 + kb + t];
            a[1] = Ps[prow1 + kb + t];
            a[2] = Ps[prow0 + kb + t + 4];
            a[3] = Ps[prow1 + kb + t + 4];
            #pragma unroll
            for (int nt = 0; nt < 8; nt++) {
                int cn = half * 64 + nt * 8 + g;
                uint32_t b0 = Vs[(kb + t) * SVm + cn];
                uint32_t b1 = Vs[(kb + t + 4) * SVm + cn];
                mma8(o[nt], a, b0, b1);
            }
        }
        __syncthreads();   // all warps done with V(kt)/P(kt) before overwrite
        if (kt + 1 < NT) { load_V(kt + 1); CP_COMMIT; }
    }

    // epilogue: normalize + pack bf16 hi/lo for the O-projection
    float inv0 = 1.f / lrow[0], inv1 = 1.f / lrow[1];
    const size_t obp = ((size_t)(b * SEQ + qt * 128 + r0)) * HID2 + h * (HD / 2);
    #pragma unroll
    for (int nt = 0; nt < 8; nt++) {
        int cp = half * 32 + nt * 4 + t;   // packed column within head
        float v00 = o[nt][0] * inv0, v01 = o[nt][1] * inv0;
        float v10 = o[nt][2] * inv1, v11 = o[nt][3] * inv1;
        uint32_t h0, l0, h1, l1;
        packsplit_bf(v00, v01, h0, l0);
        packsplit_bf(v10, v11, h1, l1);
        OutH[obp + cp]            = h0;
        OutL[obp + cp]            = l0;
        OutH[obp + 8 * HID2 + cp] = h1;
        OutL[obp + 8 * HID2 + cp] = l1;
    }
}

// ---------------- launch ----------------
extern "C" void kernel_launch(void* const* d_in, const int* in_sizes, int n_in,
                              void* d_out, int out_size)
{
    const float* hidden = (const float*)d_in[0];
    const float* Wq = (const float*)d_in[1];
    const float* bq = (const float*)d_in[2];
    const float* Wk = (const float*)d_in[3];
    const float* bk = (const float*)d_in[4];
    const float* Wv = (const float*)d_in[5];
    const float* bv = (const float*)d_in[6];
    const float* Wo = (const float*)d_in[7];
    const float* bo = (const float*)d_in[8];
    float* out = (float*)d_out;

    uint32_t *Hh, *Hl, *Wqh, *Wql, *Woh, *Wol, *Wkh, *Wkl, *Wvh, *Wvl;
    uint32_t *Qtp, *Ktp, *Vtp, *Ahp, *Alp;
    cudaGetSymbolAddress((void**)&Hh,  g_Hh);  cudaGetSymbolAddress((void**)&Hl,  g_Hl);
    cudaGetSymbolAddress((void**)&Wqh, g_Wqh); cudaGetSymbolAddress((void**)&Wql, g_Wql);
    cudaGetSymbolAddress((void**)&Woh, g_Woh); cudaGetSymbolAddress((void**)&Wol, g_Wol);
    cudaGetSymbolAddress((void**)&Wkh, g_Wkh); cudaGetSymbolAddress((void**)&Wkl, g_Wkl);
    cudaGetSymbolAddress((void**)&Wvh, g_Wvh); cudaGetSymbolAddress((void**)&Wvl, g_Wvl);
    cudaGetSymbolAddress((void**)&Qtp, g_Qt);
    cudaGetSymbolAddress((void**)&Ktp, g_Kt);  cudaGetSymbolAddress((void**)&Vtp, g_Vt);
    cudaGetSymbolAddress((void**)&Ahp, g_Ah);  cudaGetSymbolAddress((void**)&Alp, g_Al);

    cudaFuncSetAttribute(gemm_bf3<1,1>, cudaFuncAttributeMaxDynamicSharedMemorySize, GEMM_SMEM(1));
    cudaFuncSetAttribute(gemm_bf3<2,1>, cudaFuncAttributeMaxDynamicSharedMemorySize, GEMM_SMEM(2));
    cudaFuncSetAttribute(gemm_bf3<2,0>, cudaFuncAttributeMaxDynamicSharedMemorySize, GEMM_SMEM(2));
    cudaFuncSetAttribute(attn_tf32,     cudaFuncAttributeMaxDynamicSharedMemorySize, ATTN_SMEM);

    const float scale = 0.08838834764831845f;   // 1/sqrt(128)

    // one-time packs (single launch)
    {
        int total = MTOT*HID2 + 2*(HID2*HID) + 2*(HID2*HD);
        pack_all<<<(total + 255)/256, 256>>>(hidden, Wq, Wk, Wv, Wo,
                                             Hh, Hl, Wqh, Wql, Wkh, Wkl, Wvh, Wvl, Woh, Wol);
    }
    // K / V projections fused (tf32 out), N=128, BM=128
    {
        dim3 grid(1, MTOT / 128, 2);
        gemm_bf3<1,1><<<grid, 512, GEMM_SMEM(1)>>>(Hh, Hl,
                                                   Wkh, Wkl, bk, Ktp,
                                                   Wvh, Wvl, bv, Vtp,
                                                   HD, HID, 1.0f);
    }
    // Q projection (tf32 out, scale folded), BM=256
    {
        dim3 grid(HID / 128, MTOT / 256, 1);
        gemm_bf3<2,1><<<grid, 512, GEMM_SMEM(2)>>>(Hh, Hl,
                                                   Wqh, Wql, bq, Qtp,
                                                   Wqh, Wql, bq, Qtp,
                                                   HID, HID, scale);
    }
    // attention (warp-pair split, 512 thr)
    {
        dim3 grid(SEQ / 128, NH, BATCH);
        attn_tf32<<<grid, 512, ATTN_SMEM>>>(Qtp, Ktp, Vtp, Ahp, Alp);
    }
    // O projection (fp32 out) -> d_out, BM=256
    {
        dim3 grid(HID / 128, MTOT / 256, 1);
        gemm_bf3<2,0><<<grid, 512, GEMM_SMEM(2)>>>(Ahp, Alp,
                                                   Woh, Wol, bo, out,
                                                   Woh, Wol, bo, out,
                                                   HID, HID, 1.0f);
    }
}

// round 14
// speedup vs baseline: 1.3335x; 1.3335x over previous
#include <cuda_runtime.h>
#include <cstdint>

#define HID 2048
#define SEQ 2048
#define BATCH 2
#define NH 16
#define HD 128
#define MTOT (BATCH*SEQ)   /* 4096 */
#define HID2 (HID/2)

// ---------------- scratch (no allocations allowed) ----------------
__device__ uint32_t g_Hh[MTOT*HID2],  g_Hl[MTOT*HID2];    // hidden, bf16x2 packed along K
__device__ uint32_t g_Wqh[HID2*HID],  g_Wql[HID2*HID];
__device__ uint32_t g_Woh[HID2*HID],  g_Wol[HID2*HID];
__device__ uint32_t g_Wkh[HID2*HD],   g_Wkl[HID2*HD];
__device__ uint32_t g_Wvh[HID2*HD],   g_Wvl[HID2*HD];
__device__ uint32_t g_Qp[MTOT*HID2];                      // Q f16x2 d-paired, scale folded
__device__ uint32_t g_Kp[MTOT*(HD/2)];                    // K f16x2 d-paired
__device__ uint32_t g_Vd[MTOT*(HD/2)];                    // V f16x2 d-paired
__device__ uint32_t g_Vk[(MTOT/2)*HD];                    // V f16x2 key-paired
__device__ uint32_t g_Ah[MTOT*HID2],  g_Al[MTOT*HID2];    // attn out, bf16x2 packed

// ---------------- numeric helpers ----------------
__device__ __forceinline__ uint16_t f2bf(float x) {
    uint16_t r; asm("cvt.rn.bf16.f32 %0, %1;" : "=h"(r) : "f"(x)); return r;
}
__device__ __forceinline__ float bf2f(uint16_t b) {
    return __uint_as_float(((uint32_t)b) << 16);
}
__device__ __forceinline__ void packsplit_bf(float x0, float x1, uint32_t &hi, uint32_t &lo) {
    uint16_t h0 = f2bf(x0), h1 = f2bf(x1);
    hi = (uint32_t)h0 | ((uint32_t)h1 << 16);
    uint16_t l0 = f2bf(x0 - bf2f(h0)), l1 = f2bf(x1 - bf2f(h1));
    lo = (uint32_t)l0 | ((uint32_t)l1 << 16);
}
// pack (lo, hi) floats -> f16x2 (lo in low half)
__device__ __forceinline__ uint32_t pack_h2(float lo, float hi) {
    uint32_t r; asm("cvt.rn.f16x2.f32 %0, %1, %2;" : "=r"(r) : "f"(hi), "f"(lo)); return r;
}
__device__ __forceinline__ void mma16(float* d, const uint32_t* a, uint32_t b0, uint32_t b1) {
    asm volatile(
        "mma.sync.aligned.m16n8k16.row.col.f32.bf16.bf16.f32 "
        "{%0,%1,%2,%3}, {%4,%5,%6,%7}, {%8,%9}, {%0,%1,%2,%3};"
        : "+f"(d[0]), "+f"(d[1]), "+f"(d[2]), "+f"(d[3])
        : "r"(a[0]), "r"(a[1]), "r"(a[2]), "r"(a[3]), "r"(b0), "r"(b1));
}
__device__ __forceinline__ void mma16f(float* d, const uint32_t* a, uint32_t b0, uint32_t b1) {
    asm volatile(
        "mma.sync.aligned.m16n8k16.row.col.f32.f16.f16.f32 "
        "{%0,%1,%2,%3}, {%4,%5,%6,%7}, {%8,%9}, {%0,%1,%2,%3};"
        : "+f"(d[0]), "+f"(d[1]), "+f"(d[2]), "+f"(d[3])
        : "r"(a[0]), "r"(a[1]), "r"(a[2]), "r"(a[3]), "r"(b0), "r"(b1));
}
__device__ __forceinline__ uint32_t s2u(const void* p) {
    return (uint32_t)__cvta_generic_to_shared(p);
}
__device__ __forceinline__ void cp16(uint32_t dst, const void* src) {
    asm volatile("cp.async.cg.shared.global [%0], [%1], 16;" :: "r"(dst), "l"(src));
}
#define CP_COMMIT  asm volatile("cp.async.commit_group;" ::: "memory")
#define CP_WAIT(n) asm volatile("cp.async.wait_group %0;" :: "n"(n) : "memory")

// ---------------- one-time pack (ALL operand arrays, single launch) ----------------
__global__ void pack_all(
    const float* __restrict__ H,  const float* __restrict__ Wq,
    const float* __restrict__ Wk, const float* __restrict__ Wv,
    const float* __restrict__ Wo,
    uint32_t* __restrict__ Hh,  uint32_t* __restrict__ Hl,
    uint32_t* __restrict__ Wqh, uint32_t* __restrict__ Wql,
    uint32_t* __restrict__ Wkh, uint32_t* __restrict__ Wkl,
    uint32_t* __restrict__ Wvh, uint32_t* __restrict__ Wvl,
    uint32_t* __restrict__ Woh, uint32_t* __restrict__ Wol)
{
    int i = blockIdx.x * 256 + threadIdx.x;
    const int nH = MTOT * HID2, nQ = HID2 * HID, nK = HID2 * HD;
    if (i < nH) {
        float2 v = ((const float2*)H)[i];
        packsplit_bf(v.x, v.y, Hh[i], Hl[i]);
    } else if ((i -= nH) < nQ) {
        int kp = i / HID, n = i - kp * HID;
        packsplit_bf(Wq[(size_t)(2 * kp) * HID + n], Wq[(size_t)(2 * kp + 1) * HID + n],
                     Wqh[i], Wql[i]);
    } else if ((i -= nQ) < nK) {
        int kp = i / HD, n = i - kp * HD;
        packsplit_bf(Wk[(size_t)(2 * kp) * HD + n], Wk[(size_t)(2 * kp + 1) * HD + n],
                     Wkh[i], Wkl[i]);
    } else if ((i -= nK) < nK) {
        int kp = i / HD, n = i - kp * HD;
        packsplit_bf(Wv[(size_t)(2 * kp) * HD + n], Wv[(size_t)(2 * kp + 1) * HD + n],
                     Wvh[i], Wvl[i]);
    } else if ((i -= nK) < nQ) {
        int kp = i / HID, n = i - kp * HID;
        packsplit_bf(Wo[(size_t)(2 * kp) * HID + n], Wo[(size_t)(2 * kp + 1) * HID + n],
                     Woh[i], Wol[i]);
    }
}

// V repack: d-paired [seq][HD/2] -> key-paired [seq/2][HD]
__global__ void repackV(const uint32_t* __restrict__ Vd, uint32_t* __restrict__ Vk)
{
    int i = blockIdx.x * 256 + threadIdx.x;
    if (i >= (MTOT / 2) * (HD / 2)) return;
    int kp = i >> 6, j = i & 63;
    uint32_t a = Vd[(size_t)(2 * kp) * 64 + j];
    uint32_t b = Vd[(size_t)(2 * kp + 1) * 64 + j];
    Vk[(size_t)kp * HD + 2 * j]     = __byte_perm(a, b, 0x5410);  // (lo a, lo b)
    Vk[(size_t)kp * HD + 2 * j + 1] = __byte_perm(a, b, 0x7632);  // (hi a, hi b)
}

// ======================================================================
// bf16x3 GEMM, 512 threads / 16 warps (R12-proven).
// TFOUT=0: C float (+bias). TFOUT=1: C u32 f16x2 of (acc+bias)*prescale,
//          packed along N (width N/2 u32).
// ======================================================================
#define SA 20
#define SB 136
#define GEMM_SMEM(MT) ((4*(128*(MT))*SA + 4*16*SB) * 4)

template<int MT, int TFOUT>
__global__ __launch_bounds__(512) void gemm_bf3(
    const uint32_t* __restrict__ Ahp, const uint32_t* __restrict__ Alp,
    const uint32_t* __restrict__ Bh0, const uint32_t* __restrict__ Bl0,
    const float* __restrict__ bias0, void* __restrict__ C0,
    const uint32_t* __restrict__ Bh1, const uint32_t* __restrict__ Bl1,
    const float* __restrict__ bias1, void* __restrict__ C1,
    int N, int K, float prescale)
{
    constexpr int BM   = 128 * MT;
    constexpr int ASTG = BM * SA;
    constexpr int BSTG = 16 * SB;

    extern __shared__ uint32_t smg[];
    uint32_t* sAh = smg;
    uint32_t* sAl = sAh + 2*ASTG;
    uint32_t* sBh = sAl + 2*ASTG;
    uint32_t* sBl = sBh + 2*BSTG;
    const uint32_t aAh = s2u(sAh), aAl = s2u(sAl);
    const uint32_t aBh = s2u(sBh), aBl = s2u(sBl);

    const uint32_t* Bh   = blockIdx.z ? Bh1   : Bh0;
    const uint32_t* Bl   = blockIdx.z ? Bl1   : Bl0;
    const float*    bias = blockIdx.z ? bias1 : bias0;
    void*           C    = blockIdx.z ? C1    : C0;

    const int tid  = threadIdx.x;
    const int lane = tid & 31, wid = tid >> 5;
    const int g = lane >> 2, t = lane & 3;
    const int wm = (wid >> 1) * (16 * MT);
    const int wn = (wid & 1) * 64;
    const int row0 = blockIdx.y * BM;
    const int col0 = blockIdx.x * 128;
    const int K2 = K >> 1;

    float acc[MT][8][4];
    #pragma unroll
    for (int i = 0; i < MT; i++)
        #pragma unroll
        for (int j = 0; j < 8; j++)
            #pragma unroll
            for (int c = 0; c < 4; c++) acc[i][j][c] = 0.f;

    auto load_stage = [&](int kp0, int st) {
        #pragma unroll
        for (int j = 0; j < MT; j++) {
            int idx = tid + j * 512;
            int r = idx >> 2, c = (idx & 3) * 4;
            size_t go = (size_t)(row0 + r) * K2 + kp0 + c;
            uint32_t so = (uint32_t)(st * ASTG + r * SA + c) * 4;
            cp16(aAh + so, Ahp + go);
            cp16(aAl + so, Alp + go);
        }
        {
            int r = tid >> 5, c = (tid & 31) * 4;
            size_t go = (size_t)(kp0 + r) * N + col0 + c;
            uint32_t so = (uint32_t)(st * BSTG + r * SB + c) * 4;
            cp16(aBh + so, Bh + go);
            cp16(aBl + so, Bl + go);
        }
    };

    const int NIT = K / 32;
    load_stage(0, 0); CP_COMMIT;

    for (int it = 0; it < NIT; ++it) {
        const int st = it & 1;
        if (it + 1 < NIT) { load_stage((it + 1) * 16, st ^ 1); CP_COMMIT; CP_WAIT(1); }
        else              { CP_WAIT(0); }
        __syncthreads();

        const uint32_t* Ah_s = sAh + st * ASTG;
        const uint32_t* Al_s = sAl + st * ASTG;
        const uint32_t* Bh_s = sBh + st * BSTG;
        const uint32_t* Bl_s = sBl + st * BSTG;

        #pragma unroll
        for (int s = 0; s < 2; s++) {
            const int kb = s * 8;
            uint32_t ah[MT][4], al[MT][4];
            #pragma unroll
            for (int mt = 0; mt < MT; mt++) {
                int rm = wm + mt * 16 + g;
                ah[mt][0] = Ah_s[rm * SA + kb + t];
                ah[mt][1] = Ah_s[(rm + 8) * SA + kb + t];
                ah[mt][2] = Ah_s[rm * SA + kb + t + 4];
                ah[mt][3] = Ah_s[(rm + 8) * SA + kb + t + 4];
                al[mt][0] = Al_s[rm * SA + kb + t];
                al[mt][1] = Al_s[(rm + 8) * SA + kb + t];
                al[mt][2] = Al_s[rm * SA + kb + t + 4];
                al[mt][3] = Al_s[(rm + 8) * SA + kb + t + 4];
            }
            #pragma unroll
            for (int nt = 0; nt < 8; nt++) {
                int cn = wn + nt * 8 + g;
                uint32_t bh0 = Bh_s[(kb + t) * SB + cn];
                uint32_t bh1 = Bh_s[(kb + t + 4) * SB + cn];
                uint32_t bl0 = Bl_s[(kb + t) * SB + cn];
                uint32_t bl1 = Bl_s[(kb + t + 4) * SB + cn];
                #pragma unroll
                for (int mt = 0; mt < MT; mt++) {
                    mma16(acc[mt][nt], ah[mt], bh0, bh1);
                    mma16(acc[mt][nt], al[mt], bh0, bh1);
                    mma16(acc[mt][nt], ah[mt], bl0, bl1);
                }
            }
        }
        __syncthreads();
    }

    #pragma unroll
    for (int mt = 0; mt < MT; mt++) {
        int row = row0 + wm + mt * 16 + g;
        #pragma unroll
        for (int nt = 0; nt < 8; nt++) {
            int col = col0 + wn + nt * 8 + 2 * t;
            float bx = bias[col], by = bias[col + 1];
            float v00 = acc[mt][nt][0] + bx, v01 = acc[mt][nt][1] + by;
            float v10 = acc[mt][nt][2] + bx, v11 = acc[mt][nt][3] + by;
            if (TFOUT) {
                uint32_t* Cu = (uint32_t*)C;
                int N2 = N >> 1;
                Cu[(size_t)row * N2 + (col >> 1)]       = pack_h2(v00 * prescale, v01 * prescale);
                Cu[(size_t)(row + 8) * N2 + (col >> 1)] = pack_h2(v10 * prescale, v11 * prescale);
            } else {
                float* Cf = (float*)C;
                *(float2*)(Cf + (size_t)row * N + col)       = make_float2(v00, v01);
                *(float2*)(Cf + (size_t)(row + 8) * N + col) = make_float2(v10, v11);
            }
        }
    }
}

// ======================================================================
// Flash attention, fp16 m16n8k16 (2x MAC rate vs tf32-k8), 256 thr/8 warps.
// P stays in registers (C-frag -> A-frag identity for f16). K and V both
// double-buffered; ONE barrier per tile. Q/K d-paired, V key-paired f16x2.
// ======================================================================
#define SQ2 68     /* %32=4 -> A-frag banks 4g+t bijective */
#define SK2 68     /* %32=4 -> B-frag (QK) banks 4g+t     */
#define SV2 136    /* %32=8 -> B-frag (PV) banks 8t+g     */
#define ATTN_SMEM ((128*SQ2 + 2*64*SK2 + 2*32*SV2) * 4)   /* 104448 B */

__global__ __launch_bounds__(256) void attn_f16(
    const uint32_t* __restrict__ Qp, const uint32_t* __restrict__ Kp,
    const uint32_t* __restrict__ Vk,
    uint32_t* __restrict__ OutH, uint32_t* __restrict__ OutL)
{
    extern __shared__ uint32_t sm[];
    uint32_t* Qs = sm;                    // 128 x SQ2
    uint32_t* Ks = Qs + 128 * SQ2;        // 2 x 64 x SK2
    uint32_t* Vs = Ks + 2 * 64 * SK2;     // 2 x 32 x SV2
    const uint32_t aQ = s2u(Qs), aK = s2u(Ks), aV = s2u(Vs);

    const int tid  = threadIdx.x;
    const int lane = tid & 31, warp = tid >> 5;
    const int g = lane >> 2, t = lane & 3;
    const int qt = blockIdx.x, h = blockIdx.y, b = blockIdx.z;

    const size_t qrow0 = (size_t)(b * SEQ + qt * 128);

    auto load_K = [&](int tile, int st) {
        #pragma unroll
        for (int j = 0; j < 4; j++) {          // 64 rows x 16 chunks = 1024
            int idx = tid + j * 256;
            int r = idx >> 4, c = (idx & 15) * 4;
            cp16(aK + (uint32_t)(st * 64 * SK2 + r * SK2 + c) * 4,
                 Kp + ((size_t)(b * SEQ + tile * 64 + r)) * 64 + c);
        }
    };
    auto load_V = [&](int tile, int st) {
        #pragma unroll
        for (int j = 0; j < 4; j++) {          // 32 rows x 32 chunks = 1024
            int idx = tid + j * 256;
            int r = idx >> 5, c = (idx & 31) * 4;
            cp16(aV + (uint32_t)(st * 32 * SV2 + r * SV2 + c) * 4,
                 Vk + ((size_t)(b * (SEQ / 2) + tile * 32 + r)) * HD + c);
        }
    };

    // prologue: Q + K0 + V0, one group
    #pragma unroll
    for (int j = 0; j < 8; j++) {              // 128 rows x 16 chunks = 2048
        int idx = tid + j * 256;
        int r = idx >> 4, c = (idx & 15) * 4;
        cp16(aQ + (uint32_t)(r * SQ2 + c) * 4,
             Qp + (qrow0 + r) * HID2 + h * 64 + c);
    }
    load_K(0, 0);
    load_V(0, 0);
    CP_COMMIT;

    float mrow[2] = { -1e30f, -1e30f };
    float lrow[2] = { 0.f, 0.f };
    float o[16][4];
    #pragma unroll
    for (int nt = 0; nt < 16; nt++)
        #pragma unroll
        for (int c = 0; c < 4; c++) o[nt][c] = 0.f;

    const int r0 = warp * 16 + g, r1 = r0 + 8;
    const int NT = SEQ / 64;

    for (int kt = 0; kt < NT; kt++) {
        CP_WAIT(0);          // K/V(kt) landed (issued one full tile ago)
        __syncthreads();     // also guards buffer reuse from previous tile
        if (kt + 1 < NT) {
            load_K(kt + 1, (kt + 1) & 1);
            load_V(kt + 1, (kt + 1) & 1);
            CP_COMMIT;
        }

        const uint32_t* Kst = Ks + (kt & 1) * 64 * SK2;
        const uint32_t* Vst = Vs + (kt & 1) * 32 * SV2;

        // ---- S(16x64) = Q_warp @ K^T  (8 k16-chunks over d) ----
        float s[8][4];
        #pragma unroll
        for (int nt = 0; nt < 8; nt++)
            #pragma unroll
            for (int c = 0; c < 4; c++) s[nt][c] = 0.f;

        #pragma unroll
        for (int c = 0; c < 8; c++) {
            const int kb = c * 8;
            uint32_t a[4];
            a[0] = Qs[r0 * SQ2 + kb + t];
            a[1] = Qs[r1 * SQ2 + kb + t];
            a[2] = Qs[r0 * SQ2 + kb + t + 4];
            a[3] = Qs[r1 * SQ2 + kb + t + 4];
            #pragma unroll
            for (int nt = 0; nt < 8; nt++) {
                int cn = nt * 8 + g;
                uint32_t b0 = Kst[cn * SK2 + kb + t];
                uint32_t b1 = Kst[cn * SK2 + kb + t + 4];
                mma16f(s[nt], a, b0, b1);
            }
        }

        // ---- online softmax (rows r0, r1; lanes sharing row: xor 1,2) ----
        float tm0 = -1e30f, tm1 = -1e30f;
        #pragma unroll
        for (int nt = 0; nt < 8; nt++) {
            tm0 = fmaxf(tm0, fmaxf(s[nt][0], s[nt][1]));
            tm1 = fmaxf(tm1, fmaxf(s[nt][2], s[nt][3]));
        }
        tm0 = fmaxf(tm0, __shfl_xor_sync(0xffffffffu, tm0, 1));
        tm0 = fmaxf(tm0, __shfl_xor_sync(0xffffffffu, tm0, 2));
        tm1 = fmaxf(tm1, __shfl_xor_sync(0xffffffffu, tm1, 1));
        tm1 = fmaxf(tm1, __shfl_xor_sync(0xffffffffu, tm1, 2));

        float mn0 = fmaxf(mrow[0], tm0), mn1 = fmaxf(mrow[1], tm1);
        float f0 = __expf(mrow[0] - mn0), f1 = __expf(mrow[1] - mn1);
        mrow[0] = mn0; mrow[1] = mn1;
        lrow[0] *= f0; lrow[1] *= f1;
        #pragma unroll
        for (int nt = 0; nt < 16; nt++) {
            o[nt][0] *= f0; o[nt][1] *= f0;
            o[nt][2] *= f1; o[nt][3] *= f1;
        }

        // exp + pack P into A-fragment registers directly (no smem!)
        uint32_t pp[8][2];
        float ps0 = 0.f, ps1 = 0.f;
        #pragma unroll
        for (int nt = 0; nt < 8; nt++) {
            float p0 = __expf(s[nt][0] - mn0); ps0 += p0;
            float p1 = __expf(s[nt][1] - mn0); ps0 += p1;
            float p2 = __expf(s[nt][2] - mn1); ps1 += p2;
            float p3 = __expf(s[nt][3] - mn1); ps1 += p3;
            pp[nt][0] = pack_h2(p0, p1);     // row r0, key-pair nt*4+t
            pp[nt][1] = pack_h2(p2, p3);     // row r1
        }
        ps0 += __shfl_xor_sync(0xffffffffu, ps0, 1);
        ps0 += __shfl_xor_sync(0xffffffffu, ps0, 2);
        ps1 += __shfl_xor_sync(0xffffffffu, ps1, 1);
        ps1 += __shfl_xor_sync(0xffffffffu, ps1, 2);
        lrow[0] += ps0; lrow[1] += ps1;

        // ---- O(16x128) += P(16x64) @ V(64x128)  (4 k16-chunks over keys) ----
        #pragma unroll
        for (int c = 0; c < 4; c++) {
            uint32_t a[4] = { pp[2*c][0], pp[2*c][1], pp[2*c+1][0], pp[2*c+1][1] };
            const int kb = c * 8;                 // key-pair base
            #pragma unroll
            for (int nt = 0; nt < 16; nt++) {
                int cn = nt * 8 + g;
                uint32_t b0 = Vst[(kb + t) * SV2 + cn];
                uint32_t b1 = Vst[(kb + t + 4) * SV2 + cn];
                mma16f(o[nt], a, b0, b1);
            }
        }
        // no tail barrier: next tile writes the OTHER buffer; reuse of this
        // buffer is guarded by the top-of-loop barrier two iterations later.
    }

    // epilogue: normalize + pack bf16 hi/lo for the O-projection
    float inv0 = 1.f / lrow[0], inv1 = 1.f / lrow[1];
    const size_t obp = (qrow0 + r0) * HID2 + h * (HD / 2);
    #pragma unroll
    for (int nt = 0; nt < 16; nt++) {
        int cp = nt * 4 + t;
        float v00 = o[nt][0] * inv0, v01 = o[nt][1] * inv0;
        float v10 = o[nt][2] * inv1, v11 = o[nt][3] * inv1;
        uint32_t h0, l0, h1, l1;
        packsplit_bf(v00, v01, h0, l0);
        packsplit_bf(v10, v11, h1, l1);
        OutH[obp + cp]            = h0;
        OutL[obp + cp]            = l0;
        OutH[obp + 8 * HID2 + cp] = h1;
        OutL[obp + 8 * HID2 + cp] = l1;
    }
}

// ---------------- launch ----------------
extern "C" void kernel_launch(void* const* d_in, const int* in_sizes, int n_in,
                              void* d_out, int out_size)
{
    const float* hidden = (const float*)d_in[0];
    const float* Wq = (const float*)d_in[1];
    const float* bq = (const float*)d_in[2];
    const float* Wk = (const float*)d_in[3];
    const float* bk = (const float*)d_in[4];
    const float* Wv = (const float*)d_in[5];
    const float* bv = (const float*)d_in[6];
    const float* Wo = (const float*)d_in[7];
    const float* bo = (const float*)d_in[8];
    float* out = (float*)d_out;

    uint32_t *Hh, *Hl, *Wqh, *Wql, *Woh, *Wol, *Wkh, *Wkl, *Wvh, *Wvl;
    uint32_t *Qpp, *Kpp, *Vdp, *Vkp, *Ahp, *Alp;
    cudaGetSymbolAddress((void**)&Hh,  g_Hh);  cudaGetSymbolAddress((void**)&Hl,  g_Hl);
    cudaGetSymbolAddress((void**)&Wqh, g_Wqh); cudaGetSymbolAddress((void**)&Wql, g_Wql);
    cudaGetSymbolAddress((void**)&Woh, g_Woh); cudaGetSymbolAddress((void**)&Wol, g_Wol);
    cudaGetSymbolAddress((void**)&Wkh, g_Wkh); cudaGetSymbolAddress((void**)&Wkl, g_Wkl);
    cudaGetSymbolAddress((void**)&Wvh, g_Wvh); cudaGetSymbolAddress((void**)&Wvl, g_Wvl);
    cudaGetSymbolAddress((void**)&Qpp, g_Qp);
    cudaGetSymbolAddress((void**)&Kpp, g_Kp);
    cudaGetSymbolAddress((void**)&Vdp, g_Vd);  cudaGetSymbolAddress((void**)&Vkp, g_Vk);
    cudaGetSymbolAddress((void**)&Ahp, g_Ah);  cudaGetSymbolAddress((void**)&Alp, g_Al);

    cudaFuncSetAttribute(gemm_bf3<1,1>, cudaFuncAttributeMaxDynamicSharedMemorySize, GEMM_SMEM(1));
    cudaFuncSetAttribute(gemm_bf3<2,1>, cudaFuncAttributeMaxDynamicSharedMemorySize, GEMM_SMEM(2));
    cudaFuncSetAttribute(gemm_bf3<2,0>, cudaFuncAttributeMaxDynamicSharedMemorySize, GEMM_SMEM(2));
    cudaFuncSetAttribute(attn_f16,      cudaFuncAttributeMaxDynamicSharedMemorySize, ATTN_SMEM);

    const float scale = 0.08838834764831845f;   // 1/sqrt(128)

    // one-time packs (single launch)
    {
        int total = MTOT*HID2 + 2*(HID2*HID) + 2*(HID2*HD);
        pack_all<<<(total + 255)/256, 256>>>(hidden, Wq, Wk, Wv, Wo,
                                             Hh, Hl, Wqh, Wql, Wkh, Wkl, Wvh, Wvl, Woh, Wol);
    }
    // K / V projections fused (f16x2 out), N=128, BM=128
    {
        dim3 grid(1, MTOT / 128, 2);
        gemm_bf3<1,1><<<grid, 512, GEMM_SMEM(1)>>>(Hh, Hl,
                                                   Wkh, Wkl, bk, Kpp,
                                                   Wvh, Wvl, bv, Vdp,
                                                   HD, HID, 1.0f);
    }
    // V repack: d-pairs -> key-pairs
    {
        int total = (MTOT / 2) * (HD / 2);
        repackV<<<(total + 255)/256, 256>>>(Vdp, Vkp);
    }
    // Q projection (f16x2 out, scale folded), BM=256
    {
        dim3 grid(HID / 128, MTOT / 256, 1);
        gemm_bf3<2,1><<<grid, 512, GEMM_SMEM(2)>>>(Hh, Hl,
                                                   Wqh, Wql, bq, Qpp,
                                                   Wqh, Wql, bq, Qpp,
                                                   HID, HID, scale);
    }
    // attention (fp16 mma, register-resident P)
    {
        dim3 grid(SEQ / 128, NH, BATCH);
        attn_f16<<<grid, 256, ATTN_SMEM>>>(Qpp, Kpp, Vkp, Ahp, Alp);
    }
    // O projection (fp32 out) -> d_out, BM=256
    {
        dim3 grid(HID / 128, MTOT / 256, 1);
        gemm_bf3<2,0><<<grid, 512, GEMM_SMEM(2)>>>(Ahp, Alp,
                                                   Woh, Wol, bo, out,
                                                   Woh, Wol, bo, out,
                                                   HID, HID, 1.0f);
    }
}

// round 15
// speedup vs baseline: 2.2329x; 1.6745x over previous
#include <cuda_runtime.h>
#include <cstdint>

#define HID 2048
#define SEQ 2048
#define BATCH 2
#define NH 16
#define HD 128
#define MTOT (BATCH*SEQ)   /* 4096 */
#define HID2 (HID/2)

// ---------------- scratch (no allocations allowed) ----------------
__device__ uint32_t g_Hp[MTOT*HID2];     // hidden, f16x2 packed along K
__device__ uint32_t g_Wqp[HID2*HID];     // weights, f16x2 packed along K
__device__ uint32_t g_Wop[HID2*HID];
__device__ uint32_t g_Wkp[HID2*HD];
__device__ uint32_t g_Wvp[HID2*HD];
__device__ uint32_t g_Qp[MTOT*HID2];     // Q f16x2 d-paired, scale folded
__device__ uint32_t g_Kp[MTOT*(HD/2)];   // K f16x2 d-paired
__device__ uint32_t g_Vd[MTOT*(HD/2)];   // V f16x2 d-paired
__device__ uint32_t g_Vk[(MTOT/2)*HD];   // V f16x2 key-paired
__device__ uint32_t g_Ap[MTOT*HID2];     // attn out, f16x2 packed

// ---------------- numeric helpers ----------------
// pack (lo, hi) floats -> f16x2 (lo in low half)
__device__ __forceinline__ uint32_t pack_h2(float lo, float hi) {
    uint32_t r; asm("cvt.rn.f16x2.f32 %0, %1, %2;" : "=r"(r) : "f"(hi), "f"(lo)); return r;
}
__device__ __forceinline__ void mma16f(float* d, const uint32_t* a, uint32_t b0, uint32_t b1) {
    asm volatile(
        "mma.sync.aligned.m16n8k16.row.col.f32.f16.f16.f32 "
        "{%0,%1,%2,%3}, {%4,%5,%6,%7}, {%8,%9}, {%0,%1,%2,%3};"
        : "+f"(d[0]), "+f"(d[1]), "+f"(d[2]), "+f"(d[3])
        : "r"(a[0]), "r"(a[1]), "r"(a[2]), "r"(a[3]), "r"(b0), "r"(b1));
}
__device__ __forceinline__ uint32_t s2u(const void* p) {
    return (uint32_t)__cvta_generic_to_shared(p);
}
__device__ __forceinline__ void cp16(uint32_t dst, const void* src) {
    asm volatile("cp.async.cg.shared.global [%0], [%1], 16;" :: "r"(dst), "l"(src));
}
#define CP_COMMIT  asm volatile("cp.async.commit_group;" ::: "memory")
#define CP_WAIT(n) asm volatile("cp.async.wait_group %0;" :: "n"(n) : "memory")

// ---------------- one-time pack (ALL operand arrays, single launch) ----------------
__global__ void pack_all(
    const float* __restrict__ H,  const float* __restrict__ Wq,
    const float* __restrict__ Wk, const float* __restrict__ Wv,
    const float* __restrict__ Wo,
    uint32_t* __restrict__ Hp,  uint32_t* __restrict__ Wqp,
    uint32_t* __restrict__ Wkp, uint32_t* __restrict__ Wvp,
    uint32_t* __restrict__ Wop)
{
    int i = blockIdx.x * 256 + threadIdx.x;
    const int nH = MTOT * HID2, nQ = HID2 * HID, nK = HID2 * HD;
    if (i < nH) {
        float2 v = ((const float2*)H)[i];
        Hp[i] = pack_h2(v.x, v.y);
    } else if ((i -= nH) < nQ) {
        int kp = i / HID, n = i - kp * HID;
        Wqp[i] = pack_h2(Wq[(size_t)(2 * kp) * HID + n], Wq[(size_t)(2 * kp + 1) * HID + n]);
    } else if ((i -= nQ) < nK) {
        int kp = i / HD, n = i - kp * HD;
        Wkp[i] = pack_h2(Wk[(size_t)(2 * kp) * HD + n], Wk[(size_t)(2 * kp + 1) * HD + n]);
    } else if ((i -= nK) < nK) {
        int kp = i / HD, n = i - kp * HD;
        Wvp[i] = pack_h2(Wv[(size_t)(2 * kp) * HD + n], Wv[(size_t)(2 * kp + 1) * HD + n]);
    } else if ((i -= nK) < nQ) {
        int kp = i / HID, n = i - kp * HID;
        Wop[i] = pack_h2(Wo[(size_t)(2 * kp) * HID + n], Wo[(size_t)(2 * kp + 1) * HID + n]);
    }
}

// V repack: d-paired [seq][HD/2] -> key-paired [seq/2][HD]
__global__ void repackV(const uint32_t* __restrict__ Vd, uint32_t* __restrict__ Vk)
{
    int i = blockIdx.x * 256 + threadIdx.x;
    if (i >= (MTOT / 2) * (HD / 2)) return;
    int kp = i >> 6, j = i & 63;
    uint32_t a = Vd[(size_t)(2 * kp) * 64 + j];
    uint32_t b = Vd[(size_t)(2 * kp + 1) * 64 + j];
    Vk[(size_t)kp * HD + 2 * j]     = __byte_perm(a, b, 0x5410);  // (lo a, lo b)
    Vk[(size_t)kp * HD + 2 * j + 1] = __byte_perm(a, b, 0x7632);  // (hi a, hi b)
}

// ======================================================================
// Single-fp16 GEMM (1 mma per product), 512 threads / 16 warps.
// Block tile (128*MT) x 128, BK=32 (16 packed u32). Warp tile (16*MT) x 64.
// cp.async double-buffered. Fragment addressing identical to the proven
// bf16x3 kernel — only the lo-operand arrays and 2 of 3 mma are deleted.
// TFOUT=0: C float (+bias). TFOUT=1: C u32 f16x2 of (acc+bias)*prescale.
// gridDim.z selects operand set 0/1 (fused K/V projection).
// ======================================================================
#define SA 20
#define SB 136
#define GEMM_SMEM(MT) ((2*(128*(MT))*SA + 2*16*SB) * 4)   /* MT=2: 58368 B */

template<int MT, int TFOUT>
__global__ __launch_bounds__(512) void gemm_f16(
    const uint32_t* __restrict__ Ap,
    const uint32_t* __restrict__ Bp0, const float* __restrict__ bias0, void* __restrict__ C0,
    const uint32_t* __restrict__ Bp1, const float* __restrict__ bias1, void* __restrict__ C1,
    int N, int K, float prescale)
{
    constexpr int BM   = 128 * MT;
    constexpr int ASTG = BM * SA;
    constexpr int BSTG = 16 * SB;

    extern __shared__ uint32_t smg[];
    uint32_t* sA = smg;                  // 2 x ASTG
    uint32_t* sB = sA + 2*ASTG;          // 2 x BSTG
    const uint32_t aA = s2u(sA), aB = s2u(sB);

    const uint32_t* Bp   = blockIdx.z ? Bp1   : Bp0;
    const float*    bias = blockIdx.z ? bias1 : bias0;
    void*           C    = blockIdx.z ? C1    : C0;

    const int tid  = threadIdx.x;
    const int lane = tid & 31, wid = tid >> 5;
    const int g = lane >> 2, t = lane & 3;
    const int wm = (wid >> 1) * (16 * MT);
    const int wn = (wid & 1) * 64;
    const int row0 = blockIdx.y * BM;
    const int col0 = blockIdx.x * 128;
    const int K2 = K >> 1;

    float acc[MT][8][4];
    #pragma unroll
    for (int i = 0; i < MT; i++)
        #pragma unroll
        for (int j = 0; j < 8; j++)
            #pragma unroll
            for (int c = 0; c < 4; c++) acc[i][j][c] = 0.f;

    auto load_stage = [&](int kp0, int st) {
        // A: BM rows x 16 u32 -> BM*4 float4 chunks
        #pragma unroll
        for (int j = 0; j < MT; j++) {
            int idx = tid + j * 512;
            int r = idx >> 2, c = (idx & 3) * 4;
            cp16(aA + (uint32_t)(st * ASTG + r * SA + c) * 4,
                 Ap + (size_t)(row0 + r) * K2 + kp0 + c);
        }
        // B: 16 rows x 128 u32 -> 512 chunks
        {
            int r = tid >> 5, c = (tid & 31) * 4;
            cp16(aB + (uint32_t)(st * BSTG + r * SB + c) * 4,
                 Bp + (size_t)(kp0 + r) * N + col0 + c);
        }
    };

    const int NIT = K / 32;              // 16 packed rows per iter
    load_stage(0, 0); CP_COMMIT;

    for (int it = 0; it < NIT; ++it) {
        const int st = it & 1;
        if (it + 1 < NIT) { load_stage((it + 1) * 16, st ^ 1); CP_COMMIT; CP_WAIT(1); }
        else              { CP_WAIT(0); }
        __syncthreads();

        const uint32_t* A_s = sA + st * ASTG;
        const uint32_t* B_s = sB + st * BSTG;

        #pragma unroll
        for (int s = 0; s < 2; s++) {            // two k16 steps per BK=32
            const int kb = s * 8;
            uint32_t ah[MT][4];
            #pragma unroll
            for (int mt = 0; mt < MT; mt++) {
                int rm = wm + mt * 16 + g;
                ah[mt][0] = A_s[rm * SA + kb + t];
                ah[mt][1] = A_s[(rm + 8) * SA + kb + t];
                ah[mt][2] = A_s[rm * SA + kb + t + 4];
                ah[mt][3] = A_s[(rm + 8) * SA + kb + t + 4];
            }
            #pragma unroll
            for (int nt = 0; nt < 8; nt++) {
                int cn = wn + nt * 8 + g;
                uint32_t b0 = B_s[(kb + t) * SB + cn];
                uint32_t b1 = B_s[(kb + t + 4) * SB + cn];
                #pragma unroll
                for (int mt = 0; mt < MT; mt++)
                    mma16f(acc[mt][nt], ah[mt], b0, b1);
            }
        }
        __syncthreads();
    }

    #pragma unroll
    for (int mt = 0; mt < MT; mt++) {
        int row = row0 + wm + mt * 16 + g;
        #pragma unroll
        for (int nt = 0; nt < 8; nt++) {
            int col = col0 + wn + nt * 8 + 2 * t;
            float bx = bias[col], by = bias[col + 1];
            float v00 = acc[mt][nt][0] + bx, v01 = acc[mt][nt][1] + by;
            float v10 = acc[mt][nt][2] + bx, v11 = acc[mt][nt][3] + by;
            if (TFOUT) {
                uint32_t* Cu = (uint32_t*)C;
                int N2 = N >> 1;
                Cu[(size_t)row * N2 + (col >> 1)]       = pack_h2(v00 * prescale, v01 * prescale);
                Cu[(size_t)(row + 8) * N2 + (col >> 1)] = pack_h2(v10 * prescale, v11 * prescale);
            } else {
                float* Cf = (float*)C;
                *(float2*)(Cf + (size_t)row * N + col)       = make_float2(v00, v01);
                *(float2*)(Cf + (size_t)(row + 8) * N + col) = make_float2(v10, v11);
            }
        }
    }
}

// ======================================================================
// Flash attention, fp16 m16n8k16, 256 thr / 8 warps (R14-proven).
// P register-resident; K and V double-buffered; one barrier per tile.
// ======================================================================
#define SQ2 68
#define SK2 68
#define SV2 136
#define ATTN_SMEM ((128*SQ2 + 2*64*SK2 + 2*32*SV2) * 4)   /* 104448 B */

__global__ __launch_bounds__(256) void attn_f16(
    const uint32_t* __restrict__ Qp, const uint32_t* __restrict__ Kp,
    const uint32_t* __restrict__ Vk,
    uint32_t* __restrict__ OutP)
{
    extern __shared__ uint32_t sm[];
    uint32_t* Qs = sm;                    // 128 x SQ2
    uint32_t* Ks = Qs + 128 * SQ2;        // 2 x 64 x SK2
    uint32_t* Vs = Ks + 2 * 64 * SK2;     // 2 x 32 x SV2
    const uint32_t aQ = s2u(Qs), aK = s2u(Ks), aV = s2u(Vs);

    const int tid  = threadIdx.x;
    const int lane = tid & 31, warp = tid >> 5;
    const int g = lane >> 2, t = lane & 3;
    const int qt = blockIdx.x, h = blockIdx.y, b = blockIdx.z;

    const size_t qrow0 = (size_t)(b * SEQ + qt * 128);

    auto load_K = [&](int tile, int st) {
        #pragma unroll
        for (int j = 0; j < 4; j++) {
            int idx = tid + j * 256;
            int r = idx >> 4, c = (idx & 15) * 4;
            cp16(aK + (uint32_t)(st * 64 * SK2 + r * SK2 + c) * 4,
                 Kp + ((size_t)(b * SEQ + tile * 64 + r)) * 64 + c);
        }
    };
    auto load_V = [&](int tile, int st) {
        #pragma unroll
        for (int j = 0; j < 4; j++) {
            int idx = tid + j * 256;
            int r = idx >> 5, c = (idx & 31) * 4;
            cp16(aV + (uint32_t)(st * 32 * SV2 + r * SV2 + c) * 4,
                 Vk + ((size_t)(b * (SEQ / 2) + tile * 32 + r)) * HD + c);
        }
    };

    // prologue: Q + K0 + V0, one group
    #pragma unroll
    for (int j = 0; j < 8; j++) {
        int idx = tid + j * 256;
        int r = idx >> 4, c = (idx & 15) * 4;
        cp16(aQ + (uint32_t)(r * SQ2 + c) * 4,
             Qp + (qrow0 + r) * HID2 + h * 64 + c);
    }
    load_K(0, 0);
    load_V(0, 0);
    CP_COMMIT;

    float mrow[2] = { -1e30f, -1e30f };
    float lrow[2] = { 0.f, 0.f };
    float o[16][4];
    #pragma unroll
    for (int nt = 0; nt < 16; nt++)
        #pragma unroll
        for (int c = 0; c < 4; c++) o[nt][c] = 0.f;

    const int r0 = warp * 16 + g, r1 = r0 + 8;
    const int NT = SEQ / 64;

    for (int kt = 0; kt < NT; kt++) {
        CP_WAIT(0);
        __syncthreads();
        if (kt + 1 < NT) {
            load_K(kt + 1, (kt + 1) & 1);
            load_V(kt + 1, (kt + 1) & 1);
            CP_COMMIT;
        }

        const uint32_t* Kst = Ks + (kt & 1) * 64 * SK2;
        const uint32_t* Vst = Vs + (kt & 1) * 32 * SV2;

        // ---- S(16x64) = Q_warp @ K^T ----
        float s[8][4];
        #pragma unroll
        for (int nt = 0; nt < 8; nt++)
            #pragma unroll
            for (int c = 0; c < 4; c++) s[nt][c] = 0.f;

        #pragma unroll
        for (int c = 0; c < 8; c++) {
            const int kb = c * 8;
            uint32_t a[4];
            a[0] = Qs[r0 * SQ2 + kb + t];
            a[1] = Qs[r1 * SQ2 + kb + t];
            a[2] = Qs[r0 * SQ2 + kb + t + 4];
            a[3] = Qs[r1 * SQ2 + kb + t + 4];
            #pragma unroll
            for (int nt = 0; nt < 8; nt++) {
                int cn = nt * 8 + g;
                uint32_t b0 = Kst[cn * SK2 + kb + t];
                uint32_t b1 = Kst[cn * SK2 + kb + t + 4];
                mma16f(s[nt], a, b0, b1);
            }
        }

        // ---- online softmax ----
        float tm0 = -1e30f, tm1 = -1e30f;
        #pragma unroll
        for (int nt = 0; nt < 8; nt++) {
            tm0 = fmaxf(tm0, fmaxf(s[nt][0], s[nt][1]));
            tm1 = fmaxf(tm1, fmaxf(s[nt][2], s[nt][3]));
        }
        tm0 = fmaxf(tm0, __shfl_xor_sync(0xffffffffu, tm0, 1));
        tm0 = fmaxf(tm0, __shfl_xor_sync(0xffffffffu, tm0, 2));
        tm1 = fmaxf(tm1, __shfl_xor_sync(0xffffffffu, tm1, 1));
        tm1 = fmaxf(tm1, __shfl_xor_sync(0xffffffffu, tm1, 2));

        float mn0 = fmaxf(mrow[0], tm0), mn1 = fmaxf(mrow[1], tm1);
        float f0 = __expf(mrow[0] - mn0), f1 = __expf(mrow[1] - mn1);
        mrow[0] = mn0; mrow[1] = mn1;
        lrow[0] *= f0; lrow[1] *= f1;
        #pragma unroll
        for (int nt = 0; nt < 16; nt++) {
            o[nt][0] *= f0; o[nt][1] *= f0;
            o[nt][2] *= f1; o[nt][3] *= f1;
        }

        // exp + pack P directly into A-fragment registers
        uint32_t pp[8][2];
        float ps0 = 0.f, ps1 = 0.f;
        #pragma unroll
        for (int nt = 0; nt < 8; nt++) {
            float p0 = __expf(s[nt][0] - mn0); ps0 += p0;
            float p1 = __expf(s[nt][1] - mn0); ps0 += p1;
            float p2 = __expf(s[nt][2] - mn1); ps1 += p2;
            float p3 = __expf(s[nt][3] - mn1); ps1 += p3;
            pp[nt][0] = pack_h2(p0, p1);
            pp[nt][1] = pack_h2(p2, p3);
        }
        ps0 += __shfl_xor_sync(0xffffffffu, ps0, 1);
        ps0 += __shfl_xor_sync(0xffffffffu, ps0, 2);
        ps1 += __shfl_xor_sync(0xffffffffu, ps1, 1);
        ps1 += __shfl_xor_sync(0xffffffffu, ps1, 2);
        lrow[0] += ps0; lrow[1] += ps1;

        // ---- O(16x128) += P(16x64) @ V(64x128) ----
        #pragma unroll
        for (int c = 0; c < 4; c++) {
            uint32_t a[4] = { pp[2*c][0], pp[2*c][1], pp[2*c+1][0], pp[2*c+1][1] };
            const int kb = c * 8;
            #pragma unroll
            for (int nt = 0; nt < 16; nt++) {
                int cn = nt * 8 + g;
                uint32_t b0 = Vst[(kb + t) * SV2 + cn];
                uint32_t b1 = Vst[(kb + t + 4) * SV2 + cn];
                mma16f(o[nt], a, b0, b1);
            }
        }
    }

    // epilogue: normalize + pack f16x2 for the O-projection
    float inv0 = 1.f / lrow[0], inv1 = 1.f / lrow[1];
    const size_t obp = (qrow0 + r0) * HID2 + h * (HD / 2);
    #pragma unroll
    for (int nt = 0; nt < 16; nt++) {
        int cp = nt * 4 + t;
        OutP[obp + cp]            = pack_h2(o[nt][0] * inv0, o[nt][1] * inv0);
        OutP[obp + 8 * HID2 + cp] = pack_h2(o[nt][2] * inv1, o[nt][3] * inv1);
    }
}

// ---------------- launch ----------------
extern "C" void kernel_launch(void* const* d_in, const int* in_sizes, int n_in,
                              void* d_out, int out_size)
{
    const float* hidden = (const float*)d_in[0];
    const float* Wq = (const float*)d_in[1];
    const float* bq = (const float*)d_in[2];
    const float* Wk = (const float*)d_in[3];
    const float* bk = (const float*)d_in[4];
    const float* Wv = (const float*)d_in[5];
    const float* bv = (const float*)d_in[6];
    const float* Wo = (const float*)d_in[7];
    const float* bo = (const float*)d_in[8];
    float* out = (float*)d_out;

    uint32_t *Hp, *Wqp, *Wkp, *Wvp, *Wop;
    uint32_t *Qpp, *Kpp, *Vdp, *Vkp, *App;
    cudaGetSymbolAddress((void**)&Hp,  g_Hp);
    cudaGetSymbolAddress((void**)&Wqp, g_Wqp);
    cudaGetSymbolAddress((void**)&Wkp, g_Wkp);
    cudaGetSymbolAddress((void**)&Wvp, g_Wvp);
    cudaGetSymbolAddress((void**)&Wop, g_Wop);
    cudaGetSymbolAddress((void**)&Qpp, g_Qp);
    cudaGetSymbolAddress((void**)&Kpp, g_Kp);
    cudaGetSymbolAddress((void**)&Vdp, g_Vd);
    cudaGetSymbolAddress((void**)&Vkp, g_Vk);
    cudaGetSymbolAddress((void**)&App, g_Ap);

    cudaFuncSetAttribute(gemm_f16<1,1>, cudaFuncAttributeMaxDynamicSharedMemorySize, GEMM_SMEM(1));
    cudaFuncSetAttribute(gemm_f16<2,1>, cudaFuncAttributeMaxDynamicSharedMemorySize, GEMM_SMEM(2));
    cudaFuncSetAttribute(gemm_f16<2,0>, cudaFuncAttributeMaxDynamicSharedMemorySize, GEMM_SMEM(2));
    cudaFuncSetAttribute(attn_f16,      cudaFuncAttributeMaxDynamicSharedMemorySize, ATTN_SMEM);

    const float scale = 0.08838834764831845f;   // 1/sqrt(128)

    // one-time packs (single launch)
    {
        int total = MTOT*HID2 + 2*(HID2*HID) + 2*(HID2*HD);
        pack_all<<<(total + 255)/256, 256>>>(hidden, Wq, Wk, Wv, Wo,
                                             Hp, Wqp, Wkp, Wvp, Wop);
    }
    // K / V projections fused (f16x2 out), N=128, BM=128
    {
        dim3 grid(1, MTOT / 128, 2);
        gemm_f16<1,1><<<grid, 512, GEMM_SMEM(1)>>>(Hp,
                                                   Wkp, bk, Kpp,
                                                   Wvp, bv, Vdp,
                                                   HD, HID, 1.0f);
    }
    // V repack: d-pairs -> key-pairs
    {
        int total = (MTOT / 2) * (HD / 2);
        repackV<<<(total + 255)/256, 256>>>(Vdp, Vkp);
    }
    // Q projection (f16x2 out, scale folded), BM=256
    {
        dim3 grid(HID / 128, MTOT / 256, 1);
        gemm_f16<2,1><<<grid, 512, GEMM_SMEM(2)>>>(Hp,
                                                   Wqp, bq, Qpp,
                                                   Wqp, bq, Qpp,
                                                   HID, HID, scale);
    }
    // attention (fp16 mma, register-resident P)
    {
        dim3 grid(SEQ / 128, NH, BATCH);
        attn_f16<<<grid, 256, ATTN_SMEM>>>(Qpp, Kpp, Vkp, App);
    }
    // O projection (fp32 out) -> d_out, BM=256
    {
        dim3 grid(HID / 128, MTOT / 256, 1);
        gemm_f16<2,0><<<grid, 512, GEMM_SMEM(2)>>>(App,
                                                   Wop, bo, out,
                                                   Wop, bo, out,
                                                   HID, HID, 1.0f);
    }
}